// round 1
// baseline (speedup 1.0000x reference)
#include <cuda_runtime.h>

#define TB      64      // batch rows per CTA
#define RPAD    65      // row stride (floats) of [feat][row] activation buffers
#define KT      16      // k-chunk staged per step
#define WPAD    258     // weight stage row stride (floats), even for 8B-aligned float2
#define NTHREADS 256
#define OMEGA_F 30.0f

// ---------- f32x2 packed math (Blackwell FFMA2: 2x fp32 FMA throughput) ----------
static __device__ __forceinline__ unsigned long long pack2(float a, float b) {
    unsigned long long r;
    asm("mov.b64 %0, {%1, %2};" : "=l"(r) : "f"(a), "f"(b));
    return r;
}
static __device__ __forceinline__ void unpack2(unsigned long long v, float &a, float &b) {
    asm("mov.b64 {%0, %1}, %2;" : "=f"(a), "=f"(b) : "l"(v));
}
static __device__ __forceinline__ unsigned long long fma2(unsigned long long a,
                                                          unsigned long long b,
                                                          unsigned long long c) {
    unsigned long long d;
    asm("fma.rn.f32x2 %0, %1, %2, %3;" : "=l"(d) : "l"(a), "l"(b), "l"(c));
    return d;
}

// Shared memory layout (in floats)
#define SM_BUFE 0
#define SM_BUFT (256 * RPAD)
#define SM_BUFU (2 * 256 * RPAD)
#define SM_WBUF (3 * 256 * RPAD)
#define SM_XS   (SM_WBUF + KT * WPAD)
#define SM_PROB (SM_XS + 4 * RPAD)
#define SM_YACC (SM_PROB + 7 * TB)
#define SM_SCR  (SM_YACC + TB)
#define SM_TOTAL (SM_SCR + 4 * TB)

// ---------------------------------------------------------------------------
// Register-tiled fused GEMM layer over one CTA tile of TB=64 rows.
//   in  : smem activations, [K][RPAD] feature-major
//   W   : global weights, [N][K] row-major
//   out : smem activations, [N][RPAD]
//   ACT : 0 = sin(OMEGA*z), 1 = relu(z), 2 = relu(z + res)
// Each thread: 8 rows (warp-owned) x 8 cols (4 f32x2 column pairs, lane-interleaved).
// Weights staged KT rows at a time into wbuf with register prefetch of next chunk.
// Requires K % KT == 0, N in {128, 256}.
// ---------------------------------------------------------------------------
template <int NP2, int ACT>
static __device__ __forceinline__ void gemm16(
    const float* __restrict__ in, int K,
    const float* __restrict__ W, const float* __restrict__ bias,
    float* __restrict__ out, float* __restrict__ wbuf,
    const float* __restrict__ res)
{
    constexpr int N   = NP2 * 64;
    constexpr int LDN = KT * N / NTHREADS;   // global loads per thread per chunk

    const int tid  = threadIdx.x;
    const int lane = tid & 31;
    const int warp = tid >> 5;
    const int r0   = warp * 8;

    unsigned long long acc[8][NP2];
#pragma unroll
    for (int i = 0; i < 8; i++)
#pragma unroll
        for (int j = 0; j < NP2; j++) acc[i][j] = 0ull;

    // prefetch chunk 0 into registers
    float wr[LDN];
#pragma unroll
    for (int l = 0; l < LDN; l++) {
        int idx = tid + NTHREADS * l;
        int n = idx >> 4, kk = idx & 15;
        wr[l] = W[n * K + kk];
    }

    for (int k0 = 0; k0 < K; k0 += KT) {
        // commit prefetched chunk to smem
#pragma unroll
        for (int l = 0; l < LDN; l++) {
            int idx = tid + NTHREADS * l;
            int n = idx >> 4, kk = idx & 15;
            wbuf[kk * WPAD + n] = wr[l];
        }
        __syncthreads();

        // issue next chunk's global loads (latency hidden by compute below)
        if (k0 + KT < K) {
#pragma unroll
            for (int l = 0; l < LDN; l++) {
                int idx = tid + NTHREADS * l;
                int n = idx >> 4, kk = idx & 15;
                wr[l] = W[n * K + (k0 + KT) + kk];
            }
        }

#pragma unroll
        for (int kk = 0; kk < KT; kk++) {
            const float* arow = in + (k0 + kk) * RPAD + r0;
            unsigned long long a2[8];
#pragma unroll
            for (int i = 0; i < 8; i++) {
                float a = arow[i];
                a2[i] = pack2(a, a);
            }
#pragma unroll
            for (int j = 0; j < NP2; j++) {
                unsigned long long w2 =
                    *(const unsigned long long*)(wbuf + kk * WPAD + 2 * (lane + 32 * j));
#pragma unroll
                for (int i = 0; i < 8; i++) acc[i][j] = fma2(a2[i], w2, acc[i][j]);
            }
        }
        __syncthreads();
    }

    // epilogue: bias + activation, store transposed [n][row]
#pragma unroll
    for (int j = 0; j < NP2; j++) {
        int n = 2 * (lane + 32 * j);
        float b0 = __ldg(bias + n), b1 = __ldg(bias + n + 1);
#pragma unroll
        for (int i = 0; i < 8; i++) {
            float z0, z1;
            unpack2(acc[i][j], z0, z1);
            z0 += b0; z1 += b1;
            if (ACT == 0) {
                z0 = __sinf(OMEGA_F * z0);
                z1 = __sinf(OMEGA_F * z1);
            } else if (ACT == 1) {
                z0 = fmaxf(z0, 0.0f);
                z1 = fmaxf(z1, 0.0f);
            } else {
                z0 = fmaxf(z0 + res[n * RPAD + r0 + i], 0.0f);
                z1 = fmaxf(z1 + res[(n + 1) * RPAD + r0 + i], 0.0f);
            }
            out[n * RPAD + r0 + i]       = z0;
            out[(n + 1) * RPAD + r0 + i] = z1;
        }
    }
    __syncthreads();
}

// Small-K variant (single staged chunk, K <= KT). Used for pol_s1 (K=4).
template <int NP2, int ACT>
static __device__ __forceinline__ void gemm_small(
    const float* __restrict__ in, int K,
    const float* __restrict__ W, const float* __restrict__ bias,
    float* __restrict__ out, float* __restrict__ wbuf)
{
    constexpr int N = NP2 * 64;
    const int tid  = threadIdx.x;
    const int lane = tid & 31;
    const int warp = tid >> 5;
    const int r0   = warp * 8;

    for (int idx = tid; idx < K * N; idx += NTHREADS) {
        int n = idx / K;
        int kk = idx - n * K;
        wbuf[kk * WPAD + n] = W[n * K + kk];
    }
    __syncthreads();

    unsigned long long acc[8][NP2];
#pragma unroll
    for (int i = 0; i < 8; i++)
#pragma unroll
        for (int j = 0; j < NP2; j++) acc[i][j] = 0ull;

    for (int kk = 0; kk < K; kk++) {
        const float* arow = in + kk * RPAD + r0;
        unsigned long long a2[8];
#pragma unroll
        for (int i = 0; i < 8; i++) {
            float a = arow[i];
            a2[i] = pack2(a, a);
        }
#pragma unroll
        for (int j = 0; j < NP2; j++) {
            unsigned long long w2 =
                *(const unsigned long long*)(wbuf + kk * WPAD + 2 * (lane + 32 * j));
#pragma unroll
            for (int i = 0; i < 8; i++) acc[i][j] = fma2(a2[i], w2, acc[i][j]);
        }
    }

#pragma unroll
    for (int j = 0; j < NP2; j++) {
        int n = 2 * (lane + 32 * j);
        float b0 = __ldg(bias + n), b1 = __ldg(bias + n + 1);
#pragma unroll
        for (int i = 0; i < 8; i++) {
            float z0, z1;
            unpack2(acc[i][j], z0, z1);
            z0 += b0; z1 += b1;
            if (ACT == 0) {
                z0 = __sinf(OMEGA_F * z0);
                z1 = __sinf(OMEGA_F * z1);
            } else {
                z0 = fmaxf(z0, 0.0f);
                z1 = fmaxf(z1, 0.0f);
            }
            out[n * RPAD + r0 + i]       = z0;
            out[(n + 1) * RPAD + r0 + i] = z1;
        }
    }
    __syncthreads();
}

// ---------------------------------------------------------------------------
__global__ void __launch_bounds__(NTHREADS, 1)
moe_inr_kernel(
    const float* __restrict__ x,
    const float* __restrict__ enc_s1_w, const float* __restrict__ enc_s1_b,
    const float* __restrict__ enc_s2_w, const float* __restrict__ enc_s2_b,
    const float* __restrict__ res_fc1_w, const float* __restrict__ res_fc1_b,
    const float* __restrict__ res_fc2_w, const float* __restrict__ res_fc2_b,
    const float* __restrict__ res_fc3_w, const float* __restrict__ res_fc3_b,
    const float* __restrict__ pol_s1_w, const float* __restrict__ pol_s1_b,
    const float* __restrict__ pol_s2_w, const float* __restrict__ pol_s2_b,
    const float* __restrict__ gate_w, const float* __restrict__ gate_b,
    const float* __restrict__ exp_s1_w, const float* __restrict__ exp_s1_b,
    const float* __restrict__ exp_s2_w, const float* __restrict__ exp_s2_b,
    const float* __restrict__ exp_fin_w, const float* __restrict__ exp_fin_b,
    float* __restrict__ out)
{
    extern __shared__ float smem[];
    float* bufE  = smem + SM_BUFE;
    float* bufT  = smem + SM_BUFT;
    float* bufU  = smem + SM_BUFU;
    float* wbuf  = smem + SM_WBUF;
    float* xs    = smem + SM_XS;
    float* probs = smem + SM_PROB;
    float* yacc  = smem + SM_YACC;
    float* scr   = smem + SM_SCR;

    const int tid = threadIdx.x;
    const long long rowbase = (long long)blockIdx.x * TB;

    // ---- load x tile: [4][RPAD] feature-major ----
    {
        int r = tid >> 2, d = tid & 3;      // exactly 256 = 64*4
        xs[d * RPAD + r] = x[(rowbase + r) * 4 + d];
    }
    __syncthreads();

    // ---- positional encoding -> bufT rows [0,64): col = d*16 + f; f<8 sin, else cos ----
    for (int idx = tid; idx < 64 * TB; idx += NTHREADS) {
        int r = idx & 63, c = idx >> 6;
        int d = c >> 4, f = c & 15;
        float freq = exp2f((float)(f & 7)) * 3.14159265358979323846f;
        float ang  = xs[d * RPAD + r] * freq;
        bufT[c * RPAD + r] = (f < 8) ? sinf(ang) : cosf(ang);
    }
    __syncthreads();

    // ---- encoder ----
    gemm16<2, 0>(bufT, 64,  enc_s1_w,  enc_s1_b,  bufU, wbuf, nullptr);   // sin -> [128]
    gemm16<4, 0>(bufU, 128, enc_s2_w,  enc_s2_b,  bufE, wbuf, nullptr);   // sin -> h [256]
    gemm16<2, 1>(bufE, 256, res_fc1_w, res_fc1_b, bufT, wbuf, nullptr);   // relu -> [128]
    gemm16<2, 1>(bufT, 128, res_fc2_w, res_fc2_b, bufU, wbuf, nullptr);   // relu -> [128]
    gemm16<4, 2>(bufU, 128, res_fc3_w, res_fc3_b, bufE, wbuf, bufE);      // relu(r3+h) -> enc_feat

    // ---- policy ----
    gemm_small<2, 0>(xs, 4,   pol_s1_w, pol_s1_b, bufT, wbuf);            // sin -> [128]
    gemm16<2, 0>(bufT, 128, pol_s2_w, pol_s2_b, bufU, wbuf, nullptr);     // sin -> pf [128]

    // ---- gate: logits over concat(enc_feat[256], pf[128]) ----
    for (int idx = tid; idx < 7 * 384; idx += NTHREADS) wbuf[idx] = gate_w[idx];
    __syncthreads();
    for (int idx = tid; idx < 7 * TB; idx += NTHREADS) {
        int r = idx & 63, c = idx >> 6;
        const float* gw = wbuf + c * 384;
        float s = __ldg(gate_b + c);
        for (int k = 0; k < 256; k++) s += bufE[k * RPAD + r] * gw[k];
        for (int k = 0; k < 128; k++) s += bufU[k * RPAD + r] * gw[256 + k];
        probs[c * TB + r] = s;
    }
    __syncthreads();
    if (tid < TB) {
        int r = tid;
        float m = -1e30f;
        for (int c = 0; c < 7; c++) m = fmaxf(m, probs[c * TB + r]);
        float s = 0.0f, e[7];
        for (int c = 0; c < 7; c++) { e[c] = __expf(probs[c * TB + r] - m); s += e[c]; }
        float inv = 1.0f / s;
        for (int c = 0; c < 7; c++) probs[c * TB + r] = e[c] * inv;
        yacc[r] = 0.0f;
    }
    __syncthreads();

    // ---- experts ----
    for (int e = 0; e < 7; e++) {
        gemm16<4, 0>(bufE, 256, exp_s1_w + e * 65536, exp_s1_b + e * 256, bufT, wbuf, nullptr);
        gemm16<4, 0>(bufT, 256, exp_s2_w + e * 65536, exp_s2_b + e * 256, bufU, wbuf, nullptr);
        // final linear [256]->1, 4-way split reduction per row
        {
            int part = tid >> 6, r = tid & 63;
            const float* Wf = exp_fin_w + e * 256;
            float s = 0.0f;
            int k0 = part * 64;
            for (int k = k0; k < k0 + 64; k++) s += bufU[k * RPAD + r] * __ldg(Wf + k);
            scr[part * TB + r] = s;
        }
        __syncthreads();
        if (tid < TB) {
            int r = tid;
            float pred = scr[r] + scr[TB + r] + scr[2 * TB + r] + scr[3 * TB + r]
                       + __ldg(exp_fin_b + e);
            yacc[r] += probs[e * TB + r] * pred;
        }
        __syncthreads();
    }

    if (tid < TB) out[rowbase + tid] = yacc[tid];
}

// ---------------------------------------------------------------------------
extern "C" void kernel_launch(void* const* d_in, const int* in_sizes, int n_in,
                              void* d_out, int out_size)
{
    const float* x         = (const float*)d_in[0];
    const float* enc_s1_w  = (const float*)d_in[1];
    const float* enc_s1_b  = (const float*)d_in[2];
    const float* enc_s2_w  = (const float*)d_in[3];
    const float* enc_s2_b  = (const float*)d_in[4];
    const float* res_fc1_w = (const float*)d_in[5];
    const float* res_fc1_b = (const float*)d_in[6];
    const float* res_fc2_w = (const float*)d_in[7];
    const float* res_fc2_b = (const float*)d_in[8];
    const float* res_fc3_w = (const float*)d_in[9];
    const float* res_fc3_b = (const float*)d_in[10];
    const float* pol_s1_w  = (const float*)d_in[11];
    const float* pol_s1_b  = (const float*)d_in[12];
    const float* pol_s2_w  = (const float*)d_in[13];
    const float* pol_s2_b  = (const float*)d_in[14];
    const float* gate_w    = (const float*)d_in[15];
    const float* gate_b    = (const float*)d_in[16];
    const float* exp_s1_w  = (const float*)d_in[17];
    const float* exp_s1_b  = (const float*)d_in[18];
    const float* exp_s2_w  = (const float*)d_in[19];
    const float* exp_s2_b  = (const float*)d_in[20];
    const float* exp_fin_w = (const float*)d_in[21];
    const float* exp_fin_b = (const float*)d_in[22];

    int B = in_sizes[0] / 4;
    int grid = B / TB;
    size_t shmem = (size_t)SM_TOTAL * sizeof(float);

    cudaFuncSetAttribute(moe_inr_kernel,
                         cudaFuncAttributeMaxDynamicSharedMemorySize, (int)shmem);

    moe_inr_kernel<<<grid, NTHREADS, shmem>>>(
        x, enc_s1_w, enc_s1_b, enc_s2_w, enc_s2_b,
        res_fc1_w, res_fc1_b, res_fc2_w, res_fc2_b, res_fc3_w, res_fc3_b,
        pol_s1_w, pol_s1_b, pol_s2_w, pol_s2_b, gate_w, gate_b,
        exp_s1_w, exp_s1_b, exp_s2_w, exp_s2_b, exp_fin_w, exp_fin_b,
        (float*)d_out);
}